// round 12
// baseline (speedup 1.0000x reference)
#include <cuda_runtime.h>
#include <math.h>

// Shapes fixed by the problem:
//   hidden_states (8, 4096, 1024) f32, W (1024,1024) f32, b (1024) f32,
//   alpha (1) f32.  Output (8, 1, 1024) f32.
#define BATCH 8
#define SEQ   4096
#define HID   1024
#define NTHREADS 256              // 8 warps

// Bit layout (identical for x and W — consistency is all that matters):
//   chunk c, word k (0..3), bit `lane`  <->  element h = c*128 + 4*lane + k

// Scratch (__device__ globals; allocation-free rule).
__device__ uint4 g_xneg[BATCH][8];        // [batch][chunk] 4 sign words
__device__ uint4 g_xnz [BATCH][8];        // [batch][chunk] 4 nonzero words
__device__ unsigned long long g_wsum_fx;  // sum|W| in 2^-30 fixed point (memset to 0 per call)

#define FX_SCALE 1073741824.0             // 2^30

// ---------------------------------------------------------------------------
// K1: grid = 1024 + 8.
//   blocks 0..1023 : row r -> atomicAdd(g_wsum_fx, sum|W[r,:]| * 2^30)
//   blocks 1024..1031 : pack x sign/nonzero bits for batch (blockIdx-1024)
// Fixed-point u64 atomics => order-independent, bitwise deterministic.
// ---------------------------------------------------------------------------
__global__ void __launch_bounds__(NTHREADS)
prep_kernel(const float* __restrict__ x, const float* __restrict__ Wm)
{
    const int tid  = threadIdx.x;
    const int warp = tid >> 5;
    const int lane = tid & 31;

    if (blockIdx.x < HID) {
        // ---- |W| row sum ----
        const int row = blockIdx.x;
        const float4 wv = __ldg((const float4*)(Wm + (size_t)row * HID) + tid);
        float asum = fabsf(wv.x) + fabsf(wv.y) + fabsf(wv.z) + fabsf(wv.w);

        #pragma unroll
        for (int off = 16; off > 0; off >>= 1)
            asum += __shfl_xor_sync(0xffffffffu, asum, off);

        __shared__ float s_asum[8];
        if (lane == 0) s_asum[warp] = asum;
        __syncthreads();
        if (tid == 0) {
            float t = 0.0f;
            #pragma unroll
            for (int w2 = 0; w2 < 8; ++w2) t += s_asum[w2];
            atomicAdd(&g_wsum_fx, (unsigned long long)((double)t * FX_SCALE));
        }
    } else {
        // ---- pack x bits for batch b ----
        const int b = blockIdx.x - HID;
        float4 v = __ldg((const float4*)(x + (size_t)b * SEQ * HID) + warp * 32 + lane);
        const float e[4] = {v.x, v.y, v.z, v.w};

        unsigned neg[4], nz[4];
        #pragma unroll
        for (int k = 0; k < 4; ++k) {
            neg[k] = __ballot_sync(0xffffffffu, e[k] < 0.0f);
            nz [k] = __ballot_sync(0xffffffffu, e[k] != 0.0f);
        }
        if (lane == 0) {
            g_xneg[b][warp] = make_uint4(neg[0], neg[1], neg[2], neg[3]);
            g_xnz [b][warp] = make_uint4(nz [0], nz [1], nz [2], nz [3]);
        }
    }
}

// ---------------------------------------------------------------------------
// K2: one block per W row. Warp w = chunk w (one float4 of W per thread),
// batch-in-lane popcount dot; threads 0..7 read the scalar wsum (L2 broadcast)
// and write the row's 8 tanh outputs. Body is prep-shaped: no big reduces.
// ---------------------------------------------------------------------------
__global__ void __launch_bounds__(NTHREADS)
row_kernel(const float* __restrict__ Wm,
           const float* __restrict__ bias,
           const float* __restrict__ alpha,
           float* __restrict__ out)
{
    const int tid  = threadIdx.x;
    const int warp = tid >> 5;           // chunk
    const int lane = tid & 31;
    const int row  = blockIdx.x;
    const int mybatch = lane & 7;        // batch-in-lane

    // Issue loads early: W (DRAM/L2), packed x bits (L2)
    const float4 wv = __ldg((const float4*)(Wm + (size_t)row * HID) + warp * 32 + lane);
    const uint4 xn = g_xneg[mybatch][warp];
    const uint4 xz = g_xnz [mybatch][warp];

    const float we[4] = {wv.x, wv.y, wv.z, wv.w};
    const unsigned xnega[4] = {xn.x, xn.y, xn.z, xn.w};
    const unsigned xnza [4] = {xz.x, xz.y, xz.z, xz.w};

    int acc = 0;
    #pragma unroll
    for (int k = 0; k < 4; ++k) {
        unsigned wneg = __ballot_sync(0xffffffffu, we[k] < 0.0f);
        unsigned wnz  = __ballot_sync(0xffffffffu, we[k] != 0.0f);
        unsigned valid = xnza[k] & wnz;
        unsigned diff  = (xnega[k] ^ wneg) & valid;
        acc += __popc(valid) - 2 * __popc(diff);
    }

    __shared__ int s_acc[8][BATCH];      // [warp][batch]
    if (lane < BATCH) s_acc[warp][lane] = acc;    // lanes 0-7 carry batches 0-7
    __syncthreads();

    if (tid < BATCH) {
        const int b = tid;
        int dot = 0;
        #pragma unroll
        for (int w2 = 0; w2 < 8; ++w2) dot += s_acc[w2][b];

        const float wsum   = (float)((double)g_wsum_fx * (1.0 / FX_SCALE));
        const float wscale = wsum * (1.0f / ((float)HID * (float)HID));
        const float a      = fmaxf(__ldg(alpha), 1e-5f);
        const float scale  = a * wscale;
        out[b * HID + row] = tanhf(scale * (float)dot + __ldg(bias + row));
    }
}

extern "C" void kernel_launch(void* const* d_in, const int* in_sizes, int n_in,
                              void* d_out, int out_size)
{
    const float* x     = (const float*)d_in[0];
    const float* Wm    = (const float*)d_in[1];
    const float* bias  = (const float*)d_in[2];
    const float* alpha = (const float*)d_in[3];
    float* out = (float*)d_out;

    // Reset the fixed-point accumulator (graph-capturable memset node).
    void* wsum_addr = nullptr;
    cudaGetSymbolAddress(&wsum_addr, g_wsum_fx);
    cudaMemsetAsync(wsum_addr, 0, sizeof(unsigned long long));

    prep_kernel<<<HID + BATCH, NTHREADS>>>(x, Wm);
    row_kernel <<<HID, NTHREADS>>>(Wm, bias, alpha, out);
}

// round 13
// speedup vs baseline: 1.3080x; 1.3080x over previous
#include <cuda_runtime.h>
#include <math.h>

// Shapes fixed by the problem:
//   hidden_states (8, 4096, 1024) f32, W (1024,1024) f32, b (1024) f32,
//   alpha (1) f32.  Output (8, 1, 1024) f32.
#define BATCH 8
#define SEQ   4096
#define HID   1024
#define NTHREADS 256              // 8 warps
#define K1_ROWS 8                 // rows per |W|-sum block
#define K1_WBLOCKS (HID / K1_ROWS)        // 128
#define K2_ROWS 4                 // rows per dot block
#define K2_BLOCKS (HID / K2_ROWS)         // 256

// Bit layout (identical for x and W — consistency is all that matters):
//   chunk c, word k (0..3), bit `lane`  <->  element h = c*128 + 4*lane + k

// Scratch (__device__ globals; allocation-free rule). Rewritten every call.
__device__ uint4 g_xneg[BATCH][8];     // [batch][chunk] 4 sign words
__device__ uint4 g_xnz [BATCH][8];     // [batch][chunk] 4 nonzero words
__device__ float g_wpart[K1_WBLOCKS];  // 128 partial sums of |W|

// ---------------------------------------------------------------------------
// K1: grid = 128 + 8.
//   blocks 0..127  : 8 rows each -> g_wpart[blk] = sum |W[rows,:]| (MLP=8)
//   blocks 128..135: pack x sign/nonzero bits for batch (blockIdx-128)
// ---------------------------------------------------------------------------
__global__ void __launch_bounds__(NTHREADS)
prep_kernel(const float* __restrict__ x, const float* __restrict__ Wm)
{
    const int tid  = threadIdx.x;
    const int warp = tid >> 5;
    const int lane = tid & 31;

    if (blockIdx.x < K1_WBLOCKS) {
        const int row0 = blockIdx.x * K1_ROWS;

        // 8 independent 16B loads per thread — issued back-to-back
        float4 wv[K1_ROWS];
        #pragma unroll
        for (int r = 0; r < K1_ROWS; ++r)
            wv[r] = __ldg((const float4*)(Wm + (size_t)(row0 + r) * HID) + tid);

        float asum = 0.0f;
        #pragma unroll
        for (int r = 0; r < K1_ROWS; ++r)
            asum += fabsf(wv[r].x) + fabsf(wv[r].y) + fabsf(wv[r].z) + fabsf(wv[r].w);

        #pragma unroll
        for (int off = 16; off > 0; off >>= 1)
            asum += __shfl_xor_sync(0xffffffffu, asum, off);

        __shared__ float s_asum[8];
        if (lane == 0) s_asum[warp] = asum;
        __syncthreads();
        if (tid == 0) {
            float t = 0.0f;
            #pragma unroll
            for (int w2 = 0; w2 < 8; ++w2) t += s_asum[w2];
            g_wpart[blockIdx.x] = t;
        }
    } else {
        // ---- pack x bits for batch b ----
        const int b = blockIdx.x - K1_WBLOCKS;
        float4 v = __ldg((const float4*)(x + (size_t)b * SEQ * HID) + warp * 32 + lane);
        const float e[4] = {v.x, v.y, v.z, v.w};

        unsigned neg[4], nz[4];
        #pragma unroll
        for (int k = 0; k < 4; ++k) {
            neg[k] = __ballot_sync(0xffffffffu, e[k] < 0.0f);
            nz [k] = __ballot_sync(0xffffffffu, e[k] != 0.0f);
        }
        if (lane == 0) {
            g_xneg[b][warp] = make_uint4(neg[0], neg[1], neg[2], neg[3]);
            g_xnz [b][warp] = make_uint4(nz [0], nz [1], nz [2], nz [3]);
        }
    }
}

// ---------------------------------------------------------------------------
// K2: grid = 256, block handles 4 W rows. Warp w = chunk w for all 4 rows
// (4 independent LDG.128/thread). Batch-in-lane popcount dot per row.
// Warp 0 additionally reduces the 128 wpart partials (only its threads write
// output). Threads 0..31 write the block's 32 tanh outputs.
// ---------------------------------------------------------------------------
__global__ void __launch_bounds__(NTHREADS)
row_kernel(const float* __restrict__ Wm,
           const float* __restrict__ bias,
           const float* __restrict__ alpha,
           float* __restrict__ out)
{
    const int tid  = threadIdx.x;
    const int warp = tid >> 5;           // chunk
    const int lane = tid & 31;
    const int row0 = blockIdx.x * K2_ROWS;
    const int mybatch = lane & 7;        // batch-in-lane

    // 4 independent W loads (MLP=4) + mask loads, all issued early
    float4 wv[K2_ROWS];
    #pragma unroll
    for (int r = 0; r < K2_ROWS; ++r)
        wv[r] = __ldg((const float4*)(Wm + (size_t)(row0 + r) * HID) + warp * 32 + lane);

    const uint4 xn = g_xneg[mybatch][warp];
    const uint4 xz = g_xnz [mybatch][warp];
    const unsigned xnega[4] = {xn.x, xn.y, xn.z, xn.w};
    const unsigned xnza [4] = {xz.x, xz.y, xz.z, xz.w};

    int acc[K2_ROWS];
    #pragma unroll
    for (int r = 0; r < K2_ROWS; ++r) {
        const float we[4] = {wv[r].x, wv[r].y, wv[r].z, wv[r].w};
        int a = 0;
        #pragma unroll
        for (int k = 0; k < 4; ++k) {
            unsigned wneg = __ballot_sync(0xffffffffu, we[k] < 0.0f);
            unsigned wnz  = __ballot_sync(0xffffffffu, we[k] != 0.0f);
            unsigned valid = xnza[k] & wnz;
            unsigned diff  = (xnega[k] ^ wneg) & valid;
            a += __popc(valid) - 2 * __popc(diff);
        }
        acc[r] = a;
    }

    __shared__ int s_acc[8][K2_ROWS][BATCH];   // [warp][row][batch] = 1 KB
    if (lane < BATCH) {
        #pragma unroll
        for (int r = 0; r < K2_ROWS; ++r)
            s_acc[warp][r][lane] = acc[r];     // lanes 0-7 carry batches 0-7
    }

    // Warp 0: reduce the 128 wpart partials (one float4 per lane)
    float wsum = 0.0f;
    if (warp == 0) {
        float4 wp = *((const float4*)g_wpart + lane);   // 32 lanes x 4 = 128
        wsum = wp.x + wp.y + wp.z + wp.w;
        #pragma unroll
        for (int off = 16; off > 0; off >>= 1)
            wsum += __shfl_xor_sync(0xffffffffu, wsum, off);
    }
    __syncthreads();

    if (tid < 32) {
        const int r = tid >> 3;        // row within block
        const int b = tid & 7;         // batch
        int dot = 0;
        #pragma unroll
        for (int w2 = 0; w2 < 8; ++w2) dot += s_acc[w2][r][b];

        const float wscale = wsum * (1.0f / ((float)HID * (float)HID));
        const float a      = fmaxf(__ldg(alpha), 1e-5f);
        const float scale  = a * wscale;
        out[b * HID + row0 + r] = tanhf(scale * (float)dot + __ldg(bias + row0 + r));
    }
}

extern "C" void kernel_launch(void* const* d_in, const int* in_sizes, int n_in,
                              void* d_out, int out_size)
{
    const float* x     = (const float*)d_in[0];
    const float* Wm    = (const float*)d_in[1];
    const float* bias  = (const float*)d_in[2];
    const float* alpha = (const float*)d_in[3];
    float* out = (float*)d_out;

    prep_kernel<<<K1_WBLOCKS + BATCH, NTHREADS>>>(x, Wm);
    row_kernel <<<K2_BLOCKS, NTHREADS>>>(Wm, bias, alpha, out);
}